// round 4
// baseline (speedup 1.0000x reference)
#include <cuda_runtime.h>

#define NPTS 100000
#define NSAMP 16
#define CCH 64
#define CWCH 8
#define NROW (NPTS * NSAMP)   // 1600000
#define BN_EPS 1e-5f

#define QKV_TILE 16
#define QKV_TILES 10
#define QKV_ROWS (QKV_TILE * QKV_TILES)   // 160
#define QKV_GRID (NPTS / QKV_ROWS)        // 625
#define QKV_THREADS 192

// ---------------- scratch (__device__ globals: allocation-free, zero-init) ----
__device__ float g_xq[NPTS * CCH];
__device__ float g_xk[NPTS * CCH];
__device__ float g_xv[NPTS * CCH];
__device__ float g_w1[NROW * CWCH];
__device__ float4 g_t4[NROW];       // {t0,t1,t2, j as float-bits}
__device__ double g_sum[80];        // 0-2: bn1, 3-66: bn2, 67-74: bn3
__device__ double g_sqs[80];
__device__ float  g_ba[80];
__device__ float  g_bc[80];

// ---------------- k_qkv: [N,64]x[64,192] GEMM, weights register-resident ----
__global__ __launch_bounds__(QKV_THREADS) void k_qkv(
    const float* __restrict__ x,
    const float* __restrict__ Wq, const float* __restrict__ bq,
    const float* __restrict__ Wk, const float* __restrict__ bk,
    const float* __restrict__ Wv, const float* __restrict__ bv) {
    __shared__ __align__(16) float xs[QKV_TILE][CCH];
    int c = threadIdx.x;             // 0..191

    const float* W; const float* b; float* out; int cc;
    if (c < 64)       { W = Wq; b = bq; out = g_xq; cc = c; }
    else if (c < 128) { W = Wk; b = bk; out = g_xk; cc = c - 64; }
    else              { W = Wv; b = bv; out = g_xv; cc = c - 128; }

    float w[CCH];
#pragma unroll
    for (int j = 0; j < CCH; j++) w[j] = W[j * CCH + cc];
    float bb = b[cc];

    int rb0 = blockIdx.x * QKV_ROWS;
    for (int t = 0; t < QKV_TILES; t++) {
        int rb = rb0 + t * QKV_TILE;
        __syncthreads();
        for (int i = c; i < QKV_TILE * CCH / 4; i += QKV_THREADS) {
            int r = i >> 4, c4 = i & 15;
            *reinterpret_cast<float4*>(&xs[r][c4 * 4]) =
                *reinterpret_cast<const float4*>(&x[(rb + r) * CCH + c4 * 4]);
        }
        __syncthreads();

        float acc[QKV_TILE];
#pragma unroll
        for (int r = 0; r < QKV_TILE; r++) acc[r] = bb;
#pragma unroll
        for (int j4 = 0; j4 < 16; j4++) {
            float w0 = w[4 * j4], w1 = w[4 * j4 + 1], w2 = w[4 * j4 + 2], w3 = w[4 * j4 + 3];
#pragma unroll
            for (int r = 0; r < QKV_TILE; r++) {
                float4 xv = *reinterpret_cast<const float4*>(&xs[r][4 * j4]);
                acc[r] = fmaf(w0, xv.x, acc[r]);
                acc[r] = fmaf(w1, xv.y, acc[r]);
                acc[r] = fmaf(w2, xv.z, acc[r]);
                acc[r] = fmaf(w3, xv.w, acc[r]);
            }
        }
#pragma unroll
        for (int r = 0; r < QKV_TILE; r++)
            out[(rb + r) * CCH + cc] = acc[r];
    }
}

// ---------------- k_p1: t = p_r0 @ Wp1 + bp1; store {t,j}; bn1 stats --------
__global__ __launch_bounds__(256) void k_p1(
    const float* __restrict__ p, const int* __restrict__ idx,
    const float* __restrict__ Wp1, const float* __restrict__ bp1) {
    __shared__ float ss[3], sq[3];
    int tid = threadIdx.x;
    if (tid < 3) { ss[tid] = 0.f; sq[tid] = 0.f; }
    __syncthreads();
    int row = blockIdx.x * 256 + tid;
    int n = row >> 4;
    int j = idx[row];
    float dx = p[3 * j]     - p[3 * n];
    float dy = p[3 * j + 1] - p[3 * n + 1];
    float dz = p[3 * j + 2] - p[3 * n + 2];
    float t0 = bp1[0] + dx * Wp1[0] + dy * Wp1[3] + dz * Wp1[6];
    float t1 = bp1[1] + dx * Wp1[1] + dy * Wp1[4] + dz * Wp1[7];
    float t2 = bp1[2] + dx * Wp1[2] + dy * Wp1[5] + dz * Wp1[8];
    g_t4[row] = make_float4(t0, t1, t2, __int_as_float(j));
    float a0 = t0, a1 = t1, a2 = t2;
    float q0 = t0 * t0, q1 = t1 * t1, q2 = t2 * t2;
#pragma unroll
    for (int o = 16; o; o >>= 1) {
        a0 += __shfl_down_sync(0xffffffffu, a0, o);
        a1 += __shfl_down_sync(0xffffffffu, a1, o);
        a2 += __shfl_down_sync(0xffffffffu, a2, o);
        q0 += __shfl_down_sync(0xffffffffu, q0, o);
        q1 += __shfl_down_sync(0xffffffffu, q1, o);
        q2 += __shfl_down_sync(0xffffffffu, q2, o);
    }
    if ((tid & 31) == 0) {
        atomicAdd(&ss[0], a0); atomicAdd(&sq[0], q0);
        atomicAdd(&ss[1], a1); atomicAdd(&sq[1], q1);
        atomicAdd(&ss[2], a2); atomicAdd(&sq[2], q2);
    }
    __syncthreads();
    if (tid < 3) {
        atomicAdd(&g_sum[tid], (double)ss[tid]);
        atomicAdd(&g_sqs[tid], (double)sq[tid]);
    }
}

// -------- bn finalize launch: coeffs from stats, then zero consumed range ----
__global__ void k_bn(int off, int nch, const float* __restrict__ gamma,
                     const float* __restrict__ beta) {
    int i = threadIdx.x;
    if (i >= nch) return;
    double m = g_sum[off + i] / (double)NROW;
    double v = g_sqs[off + i] / (double)NROW - m * m;
    float a = gamma[i] * rsqrtf((float)v + BN_EPS);
    g_ba[off + i] = a;
    g_bc[off + i] = beta[i] - a * (float)m;
    g_sum[off + i] = 0.0;
    g_sqs[off + i] = 0.0;
}

// ---------------- k_p2: bn2 stats over r_qk ----------------
// phase A: lane = row, compute u once, stash {u,j} in smem.
// phase B: lane = channel pair (2c,2c+1), smem float4 broadcast per row.
__global__ __launch_bounds__(256) void k_p2(
    const float* __restrict__ p, const int* __restrict__ idx,
    const float* __restrict__ Wp2, const float* __restrict__ bp2) {
    __shared__ float s_wp2[3][CCH], s_bp2[CCH];
    __shared__ float s_sum[CCH], s_sq[CCH];
    __shared__ __align__(16) float4 s_uj[8][32];
    int tid = threadIdx.x;
    if (tid < CCH) {
        s_wp2[0][tid] = Wp2[tid];
        s_wp2[1][tid] = Wp2[CCH + tid];
        s_wp2[2][tid] = Wp2[2 * CCH + tid];
        s_bp2[tid] = bp2[tid];
        s_sum[tid] = 0.f; s_sq[tid] = 0.f;
    }
    float a10 = g_ba[0], a11 = g_ba[1], a12 = g_ba[2];
    float c10 = g_bc[0], c11 = g_bc[1], c12 = g_bc[2];
    __syncthreads();
    int warp = tid >> 5, lane = tid & 31;
    int base = blockIdx.x * 256 + warp * 32;   // 32 rows = 2 points
    // phase A
    {
        float4 t4 = g_t4[base + lane];
        float u0 = fmaxf(fmaf(a10, t4.x, c10), 0.f);
        float u1 = fmaxf(fmaf(a11, t4.y, c11), 0.f);
        float u2 = fmaxf(fmaf(a12, t4.z, c12), 0.f);
        s_uj[warp][lane] = make_float4(u0, u1, u2, t4.w);
    }
    __syncwarp();
    // phase B
    int c0 = lane * 2;
    int n0 = base >> 4;
    float2 wp0 = *reinterpret_cast<const float2*>(&s_wp2[0][c0]);
    float2 wp1 = *reinterpret_cast<const float2*>(&s_wp2[1][c0]);
    float2 wp2 = *reinterpret_cast<const float2*>(&s_wp2[2][c0]);
    float2 bb  = *reinterpret_cast<const float2*>(&s_bp2[c0]);
    float2 qa = *reinterpret_cast<const float2*>(&g_xq[n0 * CCH + c0]);
    float2 qb = *reinterpret_cast<const float2*>(&g_xq[(n0 + 1) * CCH + c0]);
    float sum0 = 0.f, sq0 = 0.f, sum1 = 0.f, sq1 = 0.f;
#pragma unroll
    for (int r = 0; r < 32; r++) {
        float4 uj = s_uj[warp][r];
        int jr = __float_as_int(uj.w);
        float2 xk = *reinterpret_cast<const float2*>(&g_xk[jr * CCH + c0]);
        float qs0 = (r < 16) ? qa.x : qb.x;
        float qs1 = (r < 16) ? qa.y : qb.y;
        float pr0 = bb.x + uj.x * wp0.x + uj.y * wp1.x + uj.z * wp2.x;
        float pr1 = bb.y + uj.x * wp0.y + uj.y * wp1.y + uj.z * wp2.y;
        float r0 = xk.x - qs0 + pr0;
        float r1 = xk.y - qs1 + pr1;
        sum0 += r0; sq0 = fmaf(r0, r0, sq0);
        sum1 += r1; sq1 = fmaf(r1, r1, sq1);
    }
    atomicAdd(&s_sum[c0], sum0);     atomicAdd(&s_sq[c0], sq0);
    atomicAdd(&s_sum[c0 + 1], sum1); atomicAdd(&s_sq[c0 + 1], sq1);
    __syncthreads();
    if (tid < CCH) {
        atomicAdd(&g_sum[3 + tid], (double)s_sum[tid]);
        atomicAdd(&g_sqs[3 + tid], (double)s_sq[tid]);
    }
}

// ------- k_p3: w1 = relu(bn2(r_qk)) @ Ww1 + bww1, store + bn3 stats ---------
__global__ __launch_bounds__(128) void k_p3(
    const float* __restrict__ p, const int* __restrict__ idx,
    const float* __restrict__ Wp2, const float* __restrict__ bp2,
    const float* __restrict__ Ww1, const float* __restrict__ bww1) {
    __shared__ __align__(16) float s_h[4][32][68];
    __shared__ __align__(16) float s_ww1[CCH * CWCH];
    __shared__ float s_wp2[3][CCH], s_bp2[CCH];
    __shared__ float s_ws[8], s_wq[8];
    __shared__ __align__(16) float4 s_uj[4][32];
    int tid = threadIdx.x;
    for (int i = tid; i < CCH * CWCH; i += 128) s_ww1[i] = Ww1[i];
    if (tid < CCH) {
        s_wp2[0][tid] = Wp2[tid];
        s_wp2[1][tid] = Wp2[CCH + tid];
        s_wp2[2][tid] = Wp2[2 * CCH + tid];
        s_bp2[tid] = bp2[tid];
    }
    if (tid < 8) { s_ws[tid] = 0.f; s_wq[tid] = 0.f; }
    float a10 = g_ba[0], a11 = g_ba[1], a12 = g_ba[2];
    float c10 = g_bc[0], c11 = g_bc[1], c12 = g_bc[2];
    __syncthreads();
    int warp = tid >> 5, lane = tid & 31;
    int base = blockIdx.x * 128 + warp * 32;
    // phase A
    {
        float4 t4 = g_t4[base + lane];
        float u0 = fmaxf(fmaf(a10, t4.x, c10), 0.f);
        float u1 = fmaxf(fmaf(a11, t4.y, c11), 0.f);
        float u2 = fmaxf(fmaf(a12, t4.z, c12), 0.f);
        s_uj[warp][lane] = make_float4(u0, u1, u2, t4.w);
    }
    __syncwarp();
    // phase B: lane = channel pair (2c, 2c+1)
    int c0 = lane * 2;
    int n0 = base >> 4;
    float a2_0 = g_ba[3 + c0], c2_0 = g_bc[3 + c0];
    float a2_1 = g_ba[4 + c0], c2_1 = g_bc[4 + c0];
    float2 wp0 = *reinterpret_cast<const float2*>(&s_wp2[0][c0]);
    float2 wp1 = *reinterpret_cast<const float2*>(&s_wp2[1][c0]);
    float2 wp2 = *reinterpret_cast<const float2*>(&s_wp2[2][c0]);
    float2 bb  = *reinterpret_cast<const float2*>(&s_bp2[c0]);
    float2 qa = *reinterpret_cast<const float2*>(&g_xq[n0 * CCH + c0]);
    float2 qb = *reinterpret_cast<const float2*>(&g_xq[(n0 + 1) * CCH + c0]);
#pragma unroll
    for (int r = 0; r < 32; r++) {
        float4 uj = s_uj[warp][r];
        int jr = __float_as_int(uj.w);
        float2 xk = *reinterpret_cast<const float2*>(&g_xk[jr * CCH + c0]);
        float qs0 = (r < 16) ? qa.x : qb.x;
        float qs1 = (r < 16) ? qa.y : qb.y;
        float pr0 = bb.x + uj.x * wp0.x + uj.y * wp1.x + uj.z * wp2.x;
        float pr1 = bb.y + uj.x * wp0.y + uj.y * wp1.y + uj.z * wp2.y;
        float r0 = xk.x - qs0 + pr0;
        float r1 = xk.y - qs1 + pr1;
        float2 h;
        h.x = fmaxf(fmaf(a2_0, r0, c2_0), 0.f);
        h.y = fmaxf(fmaf(a2_1, r1, c2_1), 0.f);
        *reinterpret_cast<float2*>(&s_h[warp][r][c0]) = h;
    }
    __syncwarp();
    // phase C: lane = row, 64 -> 8 matmul
    int row = base + lane;
    float hr[CCH];
    const float4* hp = reinterpret_cast<const float4*>(&s_h[warp][lane][0]);
#pragma unroll
    for (int i = 0; i < 16; i++) {
        float4 v = hp[i];
        hr[4 * i] = v.x; hr[4 * i + 1] = v.y; hr[4 * i + 2] = v.z; hr[4 * i + 3] = v.w;
    }
    float wk[8];
#pragma unroll
    for (int k = 0; k < 8; k++) wk[k] = bww1[k];
#pragma unroll
    for (int c = 0; c < CCH; c++) {
        float hc = hr[c];
        float4 wa = *reinterpret_cast<const float4*>(&s_ww1[c * 8]);
        float4 wb = *reinterpret_cast<const float4*>(&s_ww1[c * 8 + 4]);
        wk[0] = fmaf(hc, wa.x, wk[0]); wk[1] = fmaf(hc, wa.y, wk[1]);
        wk[2] = fmaf(hc, wa.z, wk[2]); wk[3] = fmaf(hc, wa.w, wk[3]);
        wk[4] = fmaf(hc, wb.x, wk[4]); wk[5] = fmaf(hc, wb.y, wk[5]);
        wk[6] = fmaf(hc, wb.z, wk[6]); wk[7] = fmaf(hc, wb.w, wk[7]);
    }
    *reinterpret_cast<float4*>(&g_w1[row * 8])     = make_float4(wk[0], wk[1], wk[2], wk[3]);
    *reinterpret_cast<float4*>(&g_w1[row * 8 + 4]) = make_float4(wk[4], wk[5], wk[6], wk[7]);
#pragma unroll
    for (int k = 0; k < 8; k++) {
        float v = wk[k], v2 = v * v;
#pragma unroll
        for (int o = 16; o; o >>= 1) {
            v  += __shfl_down_sync(0xffffffffu, v, o);
            v2 += __shfl_down_sync(0xffffffffu, v2, o);
        }
        if (lane == 0) { atomicAdd(&s_ws[k], v); atomicAdd(&s_wq[k], v2); }
    }
    __syncthreads();
    if (tid < 8) {
        atomicAdd(&g_sum[67 + tid], (double)s_ws[tid]);
        atomicAdd(&g_sqs[67 + tid], (double)s_wq[tid]);
    }
}

// ---------------- k_p4: bn3 + 8x8 + softmax + weighted sum -> out ----------
__global__ __launch_bounds__(256) void k_p4(
    const float* __restrict__ p, const int* __restrict__ idx,
    const float* __restrict__ Wp2, const float* __restrict__ bp2,
    const float* __restrict__ Ww2, const float* __restrict__ bww2,
    float* __restrict__ out) {
    __shared__ float s_wp2[3][CCH], s_bp2[CCH];
    __shared__ float s_ww2[64];
    __shared__ float s_bww2[8];
    __shared__ __align__(16) float s_w[16][16][8];
    __shared__ __align__(16) float4 s_t1r[16][16];   // {u0,u1,u2, j bits}
    int tid = threadIdx.x;
    if (tid < CCH) {
        s_wp2[0][tid] = Wp2[tid];
        s_wp2[1][tid] = Wp2[CCH + tid];
        s_wp2[2][tid] = Wp2[2 * CCH + tid];
        s_bp2[tid] = bp2[tid];
        s_ww2[tid] = Ww2[tid];
    }
    if (tid < 8) s_bww2[tid] = bww2[tid];
    __syncthreads();

    int gl = tid & 15;
    int pt = tid >> 4;
    int n = blockIdx.x * 16 + pt;
    int row = n * NSAMP + gl;

    float4 t4 = g_t4[row];
    float u0 = fmaxf(fmaf(g_ba[0], t4.x, g_bc[0]), 0.f);
    float u1 = fmaxf(fmaf(g_ba[1], t4.y, g_bc[1]), 0.f);
    float u2 = fmaxf(fmaf(g_ba[2], t4.z, g_bc[2]), 0.f);
    s_t1r[pt][gl] = make_float4(u0, u1, u2, t4.w);

    float4 wa = *reinterpret_cast<const float4*>(&g_w1[row * 8]);
    float4 wb = *reinterpret_cast<const float4*>(&g_w1[row * 8 + 4]);
    float v1[8] = {wa.x, wa.y, wa.z, wa.w, wb.x, wb.y, wb.z, wb.w};
    float uu[8];
#pragma unroll
    for (int k = 0; k < 8; k++)
        uu[k] = fmaxf(fmaf(g_ba[67 + k], v1[k], g_bc[67 + k]), 0.f);
    float w2[8];
#pragma unroll
    for (int k2 = 0; k2 < 8; k2++) {
        float acc = s_bww2[k2];
#pragma unroll
        for (int k = 0; k < 8; k++) acc = fmaf(uu[k], s_ww2[k * 8 + k2], acc);
        w2[k2] = acc;
    }
#pragma unroll
    for (int k2 = 0; k2 < 8; k2++) {
        float mx = w2[k2];
        mx = fmaxf(mx, __shfl_xor_sync(0xffffffffu, mx, 1));
        mx = fmaxf(mx, __shfl_xor_sync(0xffffffffu, mx, 2));
        mx = fmaxf(mx, __shfl_xor_sync(0xffffffffu, mx, 4));
        mx = fmaxf(mx, __shfl_xor_sync(0xffffffffu, mx, 8));
        float e = __expf(w2[k2] - mx);
        float s = e;
        s += __shfl_xor_sync(0xffffffffu, s, 1);
        s += __shfl_xor_sync(0xffffffffu, s, 2);
        s += __shfl_xor_sync(0xffffffffu, s, 4);
        s += __shfl_xor_sync(0xffffffffu, s, 8);
        w2[k2] = e / s;
    }
    *reinterpret_cast<float4*>(&s_w[pt][gl][0]) = make_float4(w2[0], w2[1], w2[2], w2[3]);
    *reinterpret_cast<float4*>(&s_w[pt][gl][4]) = make_float4(w2[4], w2[5], w2[6], w2[7]);
    __syncwarp();

    int cb = gl * 4;
    int kb = (gl & 1) * 4;
    float wp0x = s_wp2[0][cb],     wp1x = s_wp2[1][cb],     wp2x = s_wp2[2][cb],     bv0 = s_bp2[cb];
    float wp0y = s_wp2[0][cb + 1], wp1y = s_wp2[1][cb + 1], wp2y = s_wp2[2][cb + 1], bv1 = s_bp2[cb + 1];
    float wp0z = s_wp2[0][cb + 2], wp1z = s_wp2[1][cb + 2], wp2z = s_wp2[2][cb + 2], bv2 = s_bp2[cb + 2];
    float wp0w = s_wp2[0][cb + 3], wp1w = s_wp2[1][cb + 3], wp2w = s_wp2[2][cb + 3], bv3 = s_bp2[cb + 3];
    float o0 = 0.f, o1 = 0.f, o2 = 0.f, o3 = 0.f;
#pragma unroll
    for (int t = 0; t < NSAMP; t++) {
        float4 tj = s_t1r[pt][t];
        int jt = __float_as_int(tj.w);
        float4 xv = *reinterpret_cast<const float4*>(&g_xv[jt * CCH + cb]);
        float4 wt = *reinterpret_cast<const float4*>(&s_w[pt][t][kb]);
        float pr0 = bv0 + tj.x * wp0x + tj.y * wp1x + tj.z * wp2x;
        float pr1 = bv1 + tj.x * wp0y + tj.y * wp1y + tj.z * wp2y;
        float pr2 = bv2 + tj.x * wp0z + tj.y * wp1z + tj.z * wp2z;
        float pr3 = bv3 + tj.x * wp0w + tj.y * wp1w + tj.z * wp2w;
        o0 = fmaf(xv.x + pr0, wt.x, o0);
        o1 = fmaf(xv.y + pr1, wt.y, o1);
        o2 = fmaf(xv.z + pr2, wt.z, o2);
        o3 = fmaf(xv.w + pr3, wt.w, o3);
    }
    *reinterpret_cast<float4*>(&out[n * CCH + cb]) = make_float4(o0, o1, o2, o3);
}

// ---------------- launch ----------------
extern "C" void kernel_launch(void* const* d_in, const int* in_sizes, int n_in,
                              void* d_out, int out_size) {
    const float* p    = (const float*)d_in[0];
    const float* x    = (const float*)d_in[1];
    const int*   idx  = (const int*)  d_in[3];
    const float* Wq   = (const float*)d_in[4];
    const float* bq   = (const float*)d_in[5];
    const float* Wk   = (const float*)d_in[6];
    const float* bk   = (const float*)d_in[7];
    const float* Wv   = (const float*)d_in[8];
    const float* bv   = (const float*)d_in[9];
    const float* Wp1  = (const float*)d_in[10];
    const float* bp1  = (const float*)d_in[11];
    const float* gp   = (const float*)d_in[12];
    const float* betap= (const float*)d_in[13];
    const float* Wp2  = (const float*)d_in[14];
    const float* bp2  = (const float*)d_in[15];
    const float* gw1  = (const float*)d_in[16];
    const float* bw1  = (const float*)d_in[17];
    const float* Ww1  = (const float*)d_in[18];
    const float* bww1 = (const float*)d_in[19];
    const float* gw2  = (const float*)d_in[20];
    const float* bw2  = (const float*)d_in[21];
    const float* Ww2  = (const float*)d_in[22];
    const float* bww2 = (const float*)d_in[23];
    float* out = (float*)d_out;

    k_qkv<<<QKV_GRID, QKV_THREADS>>>(x, Wq, bq, Wk, bk, Wv, bv);        // 0
    k_p1<<<NROW / 256, 256>>>(p, idx, Wp1, bp1);                        // 1
    k_bn<<<1, 64>>>(0, 3, gp, betap);                                   // 2
    k_p2<<<NROW / 256, 256>>>(p, idx, Wp2, bp2);                        // 3 <- profiled
    k_bn<<<1, 64>>>(3, 64, gw1, bw1);                                   // 4
    k_p3<<<NROW / 128, 128>>>(p, idx, Wp2, bp2, Ww1, bww1);             // 5
    k_bn<<<1, 64>>>(67, 8, gw2, bw2);                                   // 6
    k_p4<<<NPTS / 16, 256>>>(p, idx, Wp2, bp2, Ww2, bww2, out);         // 7
}

// round 5
// speedup vs baseline: 1.2735x; 1.2735x over previous
#include <cuda_runtime.h>

#define NPTS 100000
#define NSAMP 16
#define CCH 64
#define CWCH 8
#define NROW (NPTS * NSAMP)   // 1600000
#define BN_EPS 1e-5f

#define QKV_TILE 16
#define QKV_TILES 10
#define QKV_ROWS (QKV_TILE * QKV_TILES)   // 160
#define QKV_GRID (NPTS / QKV_ROWS)        // 625
#define QKV_THREADS 192

// ---------------- scratch (__device__ globals: allocation-free, zero-init) ----
__device__ float g_xq[NPTS * CCH];
__device__ float g_xk[NPTS * CCH];
__device__ float g_xv[NPTS * CCH];
__device__ float g_w1[NROW * CWCH];
__device__ double g_sum[80];   // 0-2: bn1, 3-66: bn2, 67-74: bn3
__device__ double g_sqs[80];
__device__ float  g_ba[80];
__device__ float  g_bc[80];

// ---------------- k_qkv: [N,64]x[64,192] GEMM, weights register-resident ----
__global__ __launch_bounds__(QKV_THREADS) void k_qkv(
    const float* __restrict__ x,
    const float* __restrict__ Wq, const float* __restrict__ bq,
    const float* __restrict__ Wk, const float* __restrict__ bk,
    const float* __restrict__ Wv, const float* __restrict__ bv) {
    __shared__ __align__(16) float xs[QKV_TILE][CCH];
    int c = threadIdx.x;             // 0..191

    const float* W; const float* b; float* out; int cc;
    if (c < 64)       { W = Wq; b = bq; out = g_xq; cc = c; }
    else if (c < 128) { W = Wk; b = bk; out = g_xk; cc = c - 64; }
    else              { W = Wv; b = bv; out = g_xv; cc = c - 128; }

    float w[CCH];
#pragma unroll
    for (int j = 0; j < CCH; j++) w[j] = W[j * CCH + cc];
    float bb = b[cc];

    int rb0 = blockIdx.x * QKV_ROWS;
    for (int t = 0; t < QKV_TILES; t++) {
        int rb = rb0 + t * QKV_TILE;
        __syncthreads();
        for (int i = c; i < QKV_TILE * CCH / 4; i += QKV_THREADS) {
            int r = i >> 4, c4 = i & 15;
            *reinterpret_cast<float4*>(&xs[r][c4 * 4]) =
                *reinterpret_cast<const float4*>(&x[(rb + r) * CCH + c4 * 4]);
        }
        __syncthreads();

        float acc[QKV_TILE];
#pragma unroll
        for (int r = 0; r < QKV_TILE; r++) acc[r] = bb;
#pragma unroll
        for (int j4 = 0; j4 < 16; j4++) {
            float w0 = w[4 * j4], w1 = w[4 * j4 + 1], w2 = w[4 * j4 + 2], w3 = w[4 * j4 + 3];
#pragma unroll
            for (int r = 0; r < QKV_TILE; r++) {
                float4 xv = *reinterpret_cast<const float4*>(&xs[r][4 * j4]);
                acc[r] = fmaf(w0, xv.x, acc[r]);
                acc[r] = fmaf(w1, xv.y, acc[r]);
                acc[r] = fmaf(w2, xv.z, acc[r]);
                acc[r] = fmaf(w3, xv.w, acc[r]);
            }
        }
#pragma unroll
        for (int r = 0; r < QKV_TILE; r++)
            out[(rb + r) * CCH + cc] = acc[r];
    }
}

// ---------------- k_p1: bn1 stats over t1 = p_r0 @ Wp1 + bp1 ----------------
__global__ __launch_bounds__(256) void k_p1(
    const float* __restrict__ p, const int* __restrict__ idx,
    const float* __restrict__ Wp1, const float* __restrict__ bp1) {
    __shared__ float ss[3], sq[3];
    int tid = threadIdx.x;
    if (tid < 3) { ss[tid] = 0.f; sq[tid] = 0.f; }
    __syncthreads();
    int row = blockIdx.x * 256 + tid;
    int n = row >> 4;
    int j = idx[row];
    float dx = p[3 * j]     - p[3 * n];
    float dy = p[3 * j + 1] - p[3 * n + 1];
    float dz = p[3 * j + 2] - p[3 * n + 2];
    float t0 = bp1[0] + dx * Wp1[0] + dy * Wp1[3] + dz * Wp1[6];
    float t1 = bp1[1] + dx * Wp1[1] + dy * Wp1[4] + dz * Wp1[7];
    float t2 = bp1[2] + dx * Wp1[2] + dy * Wp1[5] + dz * Wp1[8];
    float a0 = t0, a1 = t1, a2 = t2;
    float q0 = t0 * t0, q1 = t1 * t1, q2 = t2 * t2;
#pragma unroll
    for (int o = 16; o; o >>= 1) {
        a0 += __shfl_down_sync(0xffffffffu, a0, o);
        a1 += __shfl_down_sync(0xffffffffu, a1, o);
        a2 += __shfl_down_sync(0xffffffffu, a2, o);
        q0 += __shfl_down_sync(0xffffffffu, q0, o);
        q1 += __shfl_down_sync(0xffffffffu, q1, o);
        q2 += __shfl_down_sync(0xffffffffu, q2, o);
    }
    if ((tid & 31) == 0) {
        atomicAdd(&ss[0], a0); atomicAdd(&sq[0], q0);
        atomicAdd(&ss[1], a1); atomicAdd(&sq[1], q1);
        atomicAdd(&ss[2], a2); atomicAdd(&sq[2], q2);
    }
    __syncthreads();
    if (tid < 3) {
        atomicAdd(&g_sum[tid], (double)ss[tid]);
        atomicAdd(&g_sqs[tid], (double)sq[tid]);
    }
}

// -------- bn finalize: coeffs from stats, then zero the consumed range -------
__global__ void k_bn(int off, int nch, const float* __restrict__ gamma,
                     const float* __restrict__ beta) {
    int i = threadIdx.x;
    if (i >= nch) return;
    double m = g_sum[off + i] / (double)NROW;
    double v = g_sqs[off + i] / (double)NROW - m * m;
    float a = gamma[i] * rsqrtf((float)v + BN_EPS);
    g_ba[off + i] = a;
    g_bc[off + i] = beta[i] - a * (float)m;
    g_sum[off + i] = 0.0;
    g_sqs[off + i] = 0.0;
}

// ---------------- k_p2: bn2 stats over r_qk ----------------
// phase A: lane = row, compute u,j once. phase B: shuffle-broadcast,
// lane = channel pair (2c, 2c+1), one LDG.64 gather per row.
__global__ __launch_bounds__(256) void k_p2(
    const float* __restrict__ p, const int* __restrict__ idx,
    const float* __restrict__ Wp1, const float* __restrict__ bp1,
    const float* __restrict__ Wp2, const float* __restrict__ bp2) {
    __shared__ float s_wp2[3][CCH], s_bp2[CCH];
    __shared__ float s_sum[CCH], s_sq[CCH];
    int tid = threadIdx.x;
    if (tid < CCH) {
        s_wp2[0][tid] = Wp2[tid];
        s_wp2[1][tid] = Wp2[CCH + tid];
        s_wp2[2][tid] = Wp2[2 * CCH + tid];
        s_bp2[tid] = bp2[tid];
        s_sum[tid] = 0.f; s_sq[tid] = 0.f;
    }
    float a10 = g_ba[0], a11 = g_ba[1], a12 = g_ba[2];
    float c10 = g_bc[0], c11 = g_bc[1], c12 = g_bc[2];
    float w00 = Wp1[0], w01 = Wp1[1], w02 = Wp1[2];
    float w10 = Wp1[3], w11 = Wp1[4], w12 = Wp1[5];
    float w20 = Wp1[6], w21 = Wp1[7], w22 = Wp1[8];
    float b0 = bp1[0], b1 = bp1[1], b2 = bp1[2];
    __syncthreads();
    int warp = tid >> 5, lane = tid & 31;
    int base = blockIdx.x * 256 + warp * 32;   // 32 rows = 2 points
    // phase A: own row
    int row = base + lane;
    int j_own = idx[row];
    int n_own = row >> 4;
    float u0, u1, u2;
    {
        float dx = p[3 * j_own]     - p[3 * n_own];
        float dy = p[3 * j_own + 1] - p[3 * n_own + 1];
        float dz = p[3 * j_own + 2] - p[3 * n_own + 2];
        float t0 = b0 + dx * w00 + dy * w10 + dz * w20;
        float t1 = b1 + dx * w01 + dy * w11 + dz * w21;
        float t2 = b2 + dx * w02 + dy * w12 + dz * w22;
        u0 = fmaxf(fmaf(a10, t0, c10), 0.f);
        u1 = fmaxf(fmaf(a11, t1, c11), 0.f);
        u2 = fmaxf(fmaf(a12, t2, c12), 0.f);
    }
    // phase B: lane = channel pair
    int c0 = lane * 2;
    int n0 = base >> 4;
    float2 wp0 = *reinterpret_cast<const float2*>(&s_wp2[0][c0]);
    float2 wp1 = *reinterpret_cast<const float2*>(&s_wp2[1][c0]);
    float2 wp2 = *reinterpret_cast<const float2*>(&s_wp2[2][c0]);
    float2 bb  = *reinterpret_cast<const float2*>(&s_bp2[c0]);
    float2 qa = *reinterpret_cast<const float2*>(&g_xq[n0 * CCH + c0]);
    float2 qb = *reinterpret_cast<const float2*>(&g_xq[(n0 + 1) * CCH + c0]);
    float sum0 = 0.f, sq0 = 0.f, sum1 = 0.f, sq1 = 0.f;
#pragma unroll
    for (int r = 0; r < 32; r++) {
        float u0r = __shfl_sync(0xffffffffu, u0, r);
        float u1r = __shfl_sync(0xffffffffu, u1, r);
        float u2r = __shfl_sync(0xffffffffu, u2, r);
        int   jr  = __shfl_sync(0xffffffffu, j_own, r);
        float2 xk = *reinterpret_cast<const float2*>(&g_xk[jr * CCH + c0]);
        float qs0 = (r < 16) ? qa.x : qb.x;
        float qs1 = (r < 16) ? qa.y : qb.y;
        float pr0 = bb.x + u0r * wp0.x + u1r * wp1.x + u2r * wp2.x;
        float pr1 = bb.y + u0r * wp0.y + u1r * wp1.y + u2r * wp2.y;
        float r0 = xk.x - qs0 + pr0;
        float r1 = xk.y - qs1 + pr1;
        sum0 += r0; sq0 = fmaf(r0, r0, sq0);
        sum1 += r1; sq1 = fmaf(r1, r1, sq1);
    }
    atomicAdd(&s_sum[c0], sum0);     atomicAdd(&s_sq[c0], sq0);
    atomicAdd(&s_sum[c0 + 1], sum1); atomicAdd(&s_sq[c0 + 1], sq1);
    __syncthreads();
    if (tid < CCH) {
        atomicAdd(&g_sum[3 + tid], (double)s_sum[tid]);
        atomicAdd(&g_sqs[3 + tid], (double)s_sq[tid]);
    }
}

// ------- k_p3: w1 = relu(bn2(r_qk)) @ Ww1 + bww1, store + bn3 stats ---------
__global__ __launch_bounds__(128) void k_p3(
    const float* __restrict__ p, const int* __restrict__ idx,
    const float* __restrict__ Wp1, const float* __restrict__ bp1,
    const float* __restrict__ Wp2, const float* __restrict__ bp2,
    const float* __restrict__ Ww1, const float* __restrict__ bww1) {
    __shared__ __align__(16) float s_h[4][32][68];
    __shared__ __align__(16) float s_ww1[CCH * CWCH];
    __shared__ float s_wp2[3][CCH], s_bp2[CCH];
    __shared__ float s_ws[8], s_wq[8];
    int tid = threadIdx.x;
    for (int i = tid; i < CCH * CWCH; i += 128) s_ww1[i] = Ww1[i];
    if (tid < CCH) {
        s_wp2[0][tid] = Wp2[tid];
        s_wp2[1][tid] = Wp2[CCH + tid];
        s_wp2[2][tid] = Wp2[2 * CCH + tid];
        s_bp2[tid] = bp2[tid];
    }
    if (tid < 8) { s_ws[tid] = 0.f; s_wq[tid] = 0.f; }
    float a10 = g_ba[0], a11 = g_ba[1], a12 = g_ba[2];
    float c10 = g_bc[0], c11 = g_bc[1], c12 = g_bc[2];
    float w00 = Wp1[0], w01 = Wp1[1], w02 = Wp1[2];
    float w10 = Wp1[3], w11 = Wp1[4], w12 = Wp1[5];
    float w20 = Wp1[6], w21 = Wp1[7], w22 = Wp1[8];
    float b0 = bp1[0], b1 = bp1[1], b2 = bp1[2];
    __syncthreads();
    int warp = tid >> 5, lane = tid & 31;
    int base = blockIdx.x * 128 + warp * 32;
    // phase A: own row
    int row = base + lane;
    int j_own = idx[row];
    int n_own = row >> 4;
    float u0, u1, u2;
    {
        float dx = p[3 * j_own]     - p[3 * n_own];
        float dy = p[3 * j_own + 1] - p[3 * n_own + 1];
        float dz = p[3 * j_own + 2] - p[3 * n_own + 2];
        float t0 = b0 + dx * w00 + dy * w10 + dz * w20;
        float t1 = b1 + dx * w01 + dy * w11 + dz * w21;
        float t2 = b2 + dx * w02 + dy * w12 + dz * w22;
        u0 = fmaxf(fmaf(a10, t0, c10), 0.f);
        u1 = fmaxf(fmaf(a11, t1, c11), 0.f);
        u2 = fmaxf(fmaf(a12, t2, c12), 0.f);
    }
    // phase B: lane = channel pair (2c, 2c+1)
    int c0 = lane * 2;
    int n0 = base >> 4;
    float a2_0 = g_ba[3 + c0], c2_0 = g_bc[3 + c0];
    float a2_1 = g_ba[4 + c0], c2_1 = g_bc[4 + c0];
    float2 wp0 = *reinterpret_cast<const float2*>(&s_wp2[0][c0]);
    float2 wp1 = *reinterpret_cast<const float2*>(&s_wp2[1][c0]);
    float2 wp2 = *reinterpret_cast<const float2*>(&s_wp2[2][c0]);
    float2 bb  = *reinterpret_cast<const float2*>(&s_bp2[c0]);
    float2 qa = *reinterpret_cast<const float2*>(&g_xq[n0 * CCH + c0]);
    float2 qb = *reinterpret_cast<const float2*>(&g_xq[(n0 + 1) * CCH + c0]);
#pragma unroll
    for (int r = 0; r < 32; r++) {
        float u0r = __shfl_sync(0xffffffffu, u0, r);
        float u1r = __shfl_sync(0xffffffffu, u1, r);
        float u2r = __shfl_sync(0xffffffffu, u2, r);
        int   jr  = __shfl_sync(0xffffffffu, j_own, r);
        float2 xk = *reinterpret_cast<const float2*>(&g_xk[jr * CCH + c0]);
        float qs0 = (r < 16) ? qa.x : qb.x;
        float qs1 = (r < 16) ? qa.y : qb.y;
        float pr0 = bb.x + u0r * wp0.x + u1r * wp1.x + u2r * wp2.x;
        float pr1 = bb.y + u0r * wp0.y + u1r * wp1.y + u2r * wp2.y;
        float r0 = xk.x - qs0 + pr0;
        float r1 = xk.y - qs1 + pr1;
        float2 h;
        h.x = fmaxf(fmaf(a2_0, r0, c2_0), 0.f);
        h.y = fmaxf(fmaf(a2_1, r1, c2_1), 0.f);
        *reinterpret_cast<float2*>(&s_h[warp][r][c0]) = h;
    }
    __syncwarp();
    // phase C: lane = row, 64 -> 8 matmul
    float hr[CCH];
    const float4* hp = reinterpret_cast<const float4*>(&s_h[warp][lane][0]);
#pragma unroll
    for (int i = 0; i < 16; i++) {
        float4 v = hp[i];
        hr[4 * i] = v.x; hr[4 * i + 1] = v.y; hr[4 * i + 2] = v.z; hr[4 * i + 3] = v.w;
    }
    float wk[8];
#pragma unroll
    for (int k = 0; k < 8; k++) wk[k] = bww1[k];
#pragma unroll
    for (int c = 0; c < CCH; c++) {
        float hc = hr[c];
        float4 wa = *reinterpret_cast<const float4*>(&s_ww1[c * 8]);
        float4 wb = *reinterpret_cast<const float4*>(&s_ww1[c * 8 + 4]);
        wk[0] = fmaf(hc, wa.x, wk[0]); wk[1] = fmaf(hc, wa.y, wk[1]);
        wk[2] = fmaf(hc, wa.z, wk[2]); wk[3] = fmaf(hc, wa.w, wk[3]);
        wk[4] = fmaf(hc, wb.x, wk[4]); wk[5] = fmaf(hc, wb.y, wk[5]);
        wk[6] = fmaf(hc, wb.z, wk[6]); wk[7] = fmaf(hc, wb.w, wk[7]);
    }
    *reinterpret_cast<float4*>(&g_w1[row * 8])     = make_float4(wk[0], wk[1], wk[2], wk[3]);
    *reinterpret_cast<float4*>(&g_w1[row * 8 + 4]) = make_float4(wk[4], wk[5], wk[6], wk[7]);
#pragma unroll
    for (int k = 0; k < 8; k++) {
        float v = wk[k], v2 = v * v;
#pragma unroll
        for (int o = 16; o; o >>= 1) {
            v  += __shfl_down_sync(0xffffffffu, v, o);
            v2 += __shfl_down_sync(0xffffffffu, v2, o);
        }
        if (lane == 0) { atomicAdd(&s_ws[k], v); atomicAdd(&s_wq[k], v2); }
    }
    __syncthreads();
    if (tid < 8) {
        atomicAdd(&g_sum[67 + tid], (double)s_ws[tid]);
        atomicAdd(&g_sqs[67 + tid], (double)s_wq[tid]);
    }
}

// ---------------- k_p4: bn3 + 8x8 + softmax + weighted sum -> out ----------
__global__ __launch_bounds__(256) void k_p4(
    const float* __restrict__ p, const int* __restrict__ idx,
    const float* __restrict__ Wp1, const float* __restrict__ bp1,
    const float* __restrict__ Wp2, const float* __restrict__ bp2,
    const float* __restrict__ Ww2, const float* __restrict__ bww2,
    float* __restrict__ out) {
    __shared__ float s_wp2[3][CCH], s_bp2[CCH];
    __shared__ float s_ww2[64];
    __shared__ float s_bww2[8];
    __shared__ __align__(16) float s_w[16][16][8];
    __shared__ __align__(16) float s_t1r[16][16][4];
    __shared__ int s_j[16][16];
    int tid = threadIdx.x;
    if (tid < CCH) {
        s_wp2[0][tid] = Wp2[tid];
        s_wp2[1][tid] = Wp2[CCH + tid];
        s_wp2[2][tid] = Wp2[2 * CCH + tid];
        s_bp2[tid] = bp2[tid];
        s_ww2[tid] = Ww2[tid];
    }
    if (tid < 8) s_bww2[tid] = bww2[tid];
    __syncthreads();

    int gl = tid & 15;
    int pt = tid >> 4;
    int n = blockIdx.x * 16 + pt;
    int row = n * NSAMP + gl;
    int j = idx[row];
    s_j[pt][gl] = j;

    float dx = p[3 * j]     - p[3 * n];
    float dy = p[3 * j + 1] - p[3 * n + 1];
    float dz = p[3 * j + 2] - p[3 * n + 2];
    float t0 = bp1[0] + dx * Wp1[0] + dy * Wp1[3] + dz * Wp1[6];
    float t1 = bp1[1] + dx * Wp1[1] + dy * Wp1[4] + dz * Wp1[7];
    float t2 = bp1[2] + dx * Wp1[2] + dy * Wp1[5] + dz * Wp1[8];
    s_t1r[pt][gl][0] = fmaxf(fmaf(g_ba[0], t0, g_bc[0]), 0.f);
    s_t1r[pt][gl][1] = fmaxf(fmaf(g_ba[1], t1, g_bc[1]), 0.f);
    s_t1r[pt][gl][2] = fmaxf(fmaf(g_ba[2], t2, g_bc[2]), 0.f);

    float4 wa = *reinterpret_cast<const float4*>(&g_w1[row * 8]);
    float4 wb = *reinterpret_cast<const float4*>(&g_w1[row * 8 + 4]);
    float v1[8] = {wa.x, wa.y, wa.z, wa.w, wb.x, wb.y, wb.z, wb.w};
    float uu[8];
#pragma unroll
    for (int k = 0; k < 8; k++)
        uu[k] = fmaxf(fmaf(g_ba[67 + k], v1[k], g_bc[67 + k]), 0.f);
    float w2[8];
#pragma unroll
    for (int k2 = 0; k2 < 8; k2++) {
        float acc = s_bww2[k2];
#pragma unroll
        for (int k = 0; k < 8; k++) acc = fmaf(uu[k], s_ww2[k * 8 + k2], acc);
        w2[k2] = acc;
    }
#pragma unroll
    for (int k2 = 0; k2 < 8; k2++) {
        float mx = w2[k2];
        mx = fmaxf(mx, __shfl_xor_sync(0xffffffffu, mx, 1));
        mx = fmaxf(mx, __shfl_xor_sync(0xffffffffu, mx, 2));
        mx = fmaxf(mx, __shfl_xor_sync(0xffffffffu, mx, 4));
        mx = fmaxf(mx, __shfl_xor_sync(0xffffffffu, mx, 8));
        float e = __expf(w2[k2] - mx);
        float s = e;
        s += __shfl_xor_sync(0xffffffffu, s, 1);
        s += __shfl_xor_sync(0xffffffffu, s, 2);
        s += __shfl_xor_sync(0xffffffffu, s, 4);
        s += __shfl_xor_sync(0xffffffffu, s, 8);
        w2[k2] = e / s;
    }
    *reinterpret_cast<float4*>(&s_w[pt][gl][0]) = make_float4(w2[0], w2[1], w2[2], w2[3]);
    *reinterpret_cast<float4*>(&s_w[pt][gl][4]) = make_float4(w2[4], w2[5], w2[6], w2[7]);
    __syncwarp();

    int cb = gl * 4;
    int kb = (gl & 1) * 4;
    float wp0x = s_wp2[0][cb],     wp1x = s_wp2[1][cb],     wp2x = s_wp2[2][cb],     bv0 = s_bp2[cb];
    float wp0y = s_wp2[0][cb + 1], wp1y = s_wp2[1][cb + 1], wp2y = s_wp2[2][cb + 1], bv1 = s_bp2[cb + 1];
    float wp0z = s_wp2[0][cb + 2], wp1z = s_wp2[1][cb + 2], wp2z = s_wp2[2][cb + 2], bv2 = s_bp2[cb + 2];
    float wp0w = s_wp2[0][cb + 3], wp1w = s_wp2[1][cb + 3], wp2w = s_wp2[2][cb + 3], bv3 = s_bp2[cb + 3];
    float o0 = 0.f, o1 = 0.f, o2 = 0.f, o3 = 0.f;
#pragma unroll
    for (int t = 0; t < NSAMP; t++) {
        int jt = s_j[pt][t];
        float ua = s_t1r[pt][t][0], ub = s_t1r[pt][t][1], uc = s_t1r[pt][t][2];
        float4 xv = *reinterpret_cast<const float4*>(&g_xv[jt * CCH + cb]);
        float4 wt = *reinterpret_cast<const float4*>(&s_w[pt][t][kb]);
        float pr0 = bv0 + ua * wp0x + ub * wp1x + uc * wp2x;
        float pr1 = bv1 + ua * wp0y + ub * wp1y + uc * wp2y;
        float pr2 = bv2 + ua * wp0z + ub * wp1z + uc * wp2z;
        float pr3 = bv3 + ua * wp0w + ub * wp1w + uc * wp2w;
        o0 = fmaf(xv.x + pr0, wt.x, o0);
        o1 = fmaf(xv.y + pr1, wt.y, o1);
        o2 = fmaf(xv.z + pr2, wt.z, o2);
        o3 = fmaf(xv.w + pr3, wt.w, o3);
    }
    *reinterpret_cast<float4*>(&out[n * CCH + cb]) = make_float4(o0, o1, o2, o3);
}

// ---------------- launch ----------------
extern "C" void kernel_launch(void* const* d_in, const int* in_sizes, int n_in,
                              void* d_out, int out_size) {
    const float* p    = (const float*)d_in[0];
    const float* x    = (const float*)d_in[1];
    const int*   idx  = (const int*)  d_in[3];
    const float* Wq   = (const float*)d_in[4];
    const float* bq   = (const float*)d_in[5];
    const float* Wk   = (const float*)d_in[6];
    const float* bk   = (const float*)d_in[7];
    const float* Wv   = (const float*)d_in[8];
    const float* bv   = (const float*)d_in[9];
    const float* Wp1  = (const float*)d_in[10];
    const float* bp1  = (const float*)d_in[11];
    const float* gp   = (const float*)d_in[12];
    const float* betap= (const float*)d_in[13];
    const float* Wp2  = (const float*)d_in[14];
    const float* bp2  = (const float*)d_in[15];
    const float* gw1  = (const float*)d_in[16];
    const float* bw1  = (const float*)d_in[17];
    const float* Ww1  = (const float*)d_in[18];
    const float* bww1 = (const float*)d_in[19];
    const float* gw2  = (const float*)d_in[20];
    const float* bw2  = (const float*)d_in[21];
    const float* Ww2  = (const float*)d_in[22];
    const float* bww2 = (const float*)d_in[23];
    float* out = (float*)d_out;

    k_qkv<<<QKV_GRID, QKV_THREADS>>>(x, Wq, bq, Wk, bk, Wv, bv);           // 0
    k_p1<<<NROW / 256, 256>>>(p, idx, Wp1, bp1);                           // 1
    k_bn<<<1, 64>>>(0, 3, gp, betap);                                      // 2
    k_p2<<<NROW / 256, 256>>>(p, idx, Wp1, bp1, Wp2, bp2);                 // 3 <- profiled
    k_bn<<<1, 64>>>(3, 64, gw1, bw1);                                      // 4
    k_p3<<<NROW / 128, 128>>>(p, idx, Wp1, bp1, Wp2, bp2, Ww1, bww1);      // 5
    k_bn<<<1, 64>>>(67, 8, gw2, bw2);                                      // 6
    k_p4<<<NPTS / 16, 256>>>(p, idx, Wp1, bp1, Wp2, bp2, Ww2, bww2, out);  // 7
}